// round 7
// baseline (speedup 1.0000x reference)
#include <cuda_runtime.h>

// Shapes fixed by the reference: n=16, c=3, h=w=512
#define HW      262144          // 512*512
#define NB      16
#define CC      3
#define NHW     (NB * HW)       // 4194304 spatial positions (n,1,h,w)
#define HW4     (HW / 4)        // float4 elements per channel plane = 65536 = 2^16
#define NVEC    (NHW / 4)       // float4 elements in seg = 1048576

#define NBLOCKS  1024
#define NTHREADS 256
#define ITERS    (NVEC / (NBLOCKS * NTHREADS))   // = 4, exact tiling

// Per-block partials (device globals; no allocation allowed).
// Every slot is overwritten on every call -> fully deterministic.
__device__ float        g_part_ts[NBLOCKS];
__device__ float        g_part_ps[NBLOCKS];
__device__ unsigned int g_part_ct[NBLOCKS];
// Completion counter: zero-initialized at module load; the last block resets
// it to 0 after use, so every call (and every graph replay) starts clean.
__device__ unsigned int g_done;

// Streaming (evict-first) float4 load: data is single-use per launch.
static __device__ __forceinline__ float4 ldcs4(const float4* p) {
    return __ldcs(p);
}

__global__ void __launch_bounds__(NTHREADS)
wmse_reduce_kernel(const float4* __restrict__ x,
                   const float4* __restrict__ ae,
                   const float4* __restrict__ seg,
                   float* __restrict__ out)
{
    float ts = 0.f;        // total sum of diff^2 (all positions, over channels)
    float ps = 0.f;        // sum of diff^2 where seg > 0.5
    unsigned int cnt = 0;  // count of positive spatial positions

    const int stride = NBLOCKS * NTHREADS;
    int v = blockIdx.x * NTHREADS + threadIdx.x;

    #pragma unroll
    for (int it = 0; it < ITERS; ++it, v += stride) {
        // v indexes float4s in the (n,1,h,w) seg tensor. HW4 = 2^16, and HW is
        // divisible by 4, so a float4 never straddles an image boundary.
        const int n_i  = v >> 16;                    // image index  (v / HW4)
        const int s    = v & (HW4 - 1);              // float4 offset within plane
        const int base = n_i * (CC * HW4) + s;       // channel 0 of this image

        const float4 sg = ldcs4(seg + v);
        const float4 x0 = ldcs4(x + base);
        const float4 x1 = ldcs4(x + base + HW4);
        const float4 x2 = ldcs4(x + base + 2 * HW4);
        const float4 a0 = ldcs4(ae + base);
        const float4 a1 = ldcs4(ae + base + HW4);
        const float4 a2 = ldcs4(ae + base + 2 * HW4);

        // Select-form (branchless): straight-line predicated SASS.
        {
            float d0 = a0.x - x0.x, d1 = a1.x - x1.x, d2 = a2.x - x2.x;
            float d  = d0 * d0 + d1 * d1 + d2 * d2;
            ts += d;
            const bool p = sg.x > 0.5f;
            ps  += p ? d : 0.f;
            cnt += p ? 1u : 0u;
        }
        {
            float d0 = a0.y - x0.y, d1 = a1.y - x1.y, d2 = a2.y - x2.y;
            float d  = d0 * d0 + d1 * d1 + d2 * d2;
            ts += d;
            const bool p = sg.y > 0.5f;
            ps  += p ? d : 0.f;
            cnt += p ? 1u : 0u;
        }
        {
            float d0 = a0.z - x0.z, d1 = a1.z - x1.z, d2 = a2.z - x2.z;
            float d  = d0 * d0 + d1 * d1 + d2 * d2;
            ts += d;
            const bool p = sg.z > 0.5f;
            ps  += p ? d : 0.f;
            cnt += p ? 1u : 0u;
        }
        {
            float d0 = a0.w - x0.w, d1 = a1.w - x1.w, d2 = a2.w - x2.w;
            float d  = d0 * d0 + d1 * d1 + d2 * d2;
            ts += d;
            const bool p = sg.w > 0.5f;
            ps  += p ? d : 0.f;
            cnt += p ? 1u : 0u;
        }
    }

    // ---- warp reduction (fixed tree order) ----
    #pragma unroll
    for (int off = 16; off > 0; off >>= 1) {
        ts  += __shfl_down_sync(0xffffffffu, ts,  off);
        ps  += __shfl_down_sync(0xffffffffu, ps,  off);
        cnt += __shfl_down_sync(0xffffffffu, cnt, off);
    }

    // ---- block reduction via shared memory (fixed order) ----
    __shared__ float        s_ts[NTHREADS / 32];
    __shared__ float        s_ps[NTHREADS / 32];
    __shared__ unsigned int s_ct[NTHREADS / 32];
    __shared__ bool         s_is_last;

    const int tid  = threadIdx.x;
    const int lane = tid & 31;
    const int wid  = tid >> 5;
    if (lane == 0) { s_ts[wid] = ts; s_ps[wid] = ps; s_ct[wid] = cnt; }
    __syncthreads();

    if (tid == 0) {
        float tsum = 0.f, psum = 0.f;
        unsigned int c = 0;
        #pragma unroll
        for (int i = 0; i < NTHREADS / 32; ++i) {
            tsum += s_ts[i]; psum += s_ps[i]; c += s_ct[i];
        }
        g_part_ts[blockIdx.x] = tsum;
        g_part_ps[blockIdx.x] = psum;
        g_part_ct[blockIdx.x] = c;

        // Publish partials, then signal completion.
        __threadfence();
        const unsigned int prev = atomicAdd(&g_done, 1u);
        s_is_last = (prev == NBLOCKS - 1u);
    }
    __syncthreads();

    if (!s_is_last) return;

    // ================= last CTA: fused deterministic epilogue =================
    __threadfence();  // acquire: order partials reads after the counter observation

    // Each thread sums NBLOCKS/NTHREADS = 4 slots in fixed sequential order.
    // __ldcg: read through L2 (partials were just written by other SMs).
    double fts = 0.0, fps = 0.0;
    unsigned long long fct = 0;
    #pragma unroll
    for (int i = 0; i < NBLOCKS / NTHREADS; ++i) {
        const int idx = tid + i * NTHREADS;
        fts += (double)__ldcg(&g_part_ts[idx]);
        fps += (double)__ldcg(&g_part_ps[idx]);
        fct += (unsigned long long)__ldcg(&g_part_ct[idx]);
    }

    // Fixed-topology shared-memory tree reduction (deterministic).
    __shared__ double d_ts[NTHREADS];
    __shared__ double d_ps[NTHREADS];
    __shared__ unsigned long long d_ct[NTHREADS];
    d_ts[tid] = fts; d_ps[tid] = fps; d_ct[tid] = fct;
    __syncthreads();

    #pragma unroll
    for (int off = NTHREADS / 2; off > 0; off >>= 1) {
        if (tid < off) {
            d_ts[tid] += d_ts[tid + off];
            d_ps[tid] += d_ps[tid + off];
            d_ct[tid] += d_ct[tid + off];
        }
        __syncthreads();
    }

    if (tid == 0) {
        const double pos_num   = (double)d_ct[0];
        const double total     = (double)NHW;
        const double neg_num   = total - pos_num;
        const double pos_ratio = pos_num / total;
        const double neg_ratio = 1.0 - pos_ratio;
        const double cf        = (double)CC;
        const double pos_sum   = d_ps[0];
        const double neg_sum   = d_ts[0] - d_ps[0];
        const double mse_pos   = pos_sum / (pos_num * cf);
        const double mse_neg   = neg_sum / (neg_num * cf);
        out[0] = (float)(pos_ratio * mse_neg + neg_ratio * mse_pos);

        g_done = 0;   // reset for the next call / graph replay
    }
}

extern "C" void kernel_launch(void* const* d_in, const int* in_sizes, int n_in,
                              void* d_out, int out_size)
{
    const float4* x   = (const float4*)d_in[0];   // x       (16,3,512,512) f32
    const float4* ae  = (const float4*)d_in[1];   // out_ae  (16,3,512,512) f32
    const float4* seg = (const float4*)d_in[2];   // out_seg (16,1,512,512) f32
    float* out = (float*)d_out;

    wmse_reduce_kernel<<<NBLOCKS, NTHREADS>>>(x, ae, seg, out);
}

// round 11
// speedup vs baseline: 1.0444x; 1.0444x over previous
#include <cuda_runtime.h>

// Shapes fixed by the reference: n=16, c=3, h=w=512
#define HW      262144          // 512*512
#define NB      16
#define CC      3
#define NHW     (NB * HW)       // 4194304 spatial positions (n,1,h,w)
#define HW4     (HW / 4)        // float4 elements per channel plane = 65536 = 2^16
#define NVEC    (NHW / 4)       // float4 elements in seg = 1048576

// Single-wave persistent grid: 6 CTAs/SM x 148 SMs = 888 CTAs, all co-resident.
#define NBLOCKS   888
#define NTHREADS  256
#define TOTTHREADS (NBLOCKS * NTHREADS)          // 227328
#define FULL_ITERS 4                             // 4 * 227328 = 909312
#define REM        (NVEC - FULL_ITERS * TOTTHREADS)  // 139264 remainder float4s

// Per-block partials (device globals; no allocation allowed).
__device__ float        g_part_ts[NBLOCKS];
__device__ float        g_part_ps[NBLOCKS];
__device__ unsigned int g_part_ct[NBLOCKS];
// Completion counter: zero-init at load; last block resets it each call.
__device__ unsigned int g_done;

// Streaming (evict-first) float4 load: data is single-use per launch.
static __device__ __forceinline__ float4 ldcs4(const float4* p) {
    return __ldcs(p);
}

// One float4-group of work: seg lane + 3 channels of x/ae.
static __device__ __forceinline__ void do_group(
    const float4* __restrict__ x, const float4* __restrict__ ae,
    const float4* __restrict__ seg, int v,
    float& ts, float& ps, unsigned int& cnt)
{
    const int n_i  = v >> 16;                    // image index  (v / HW4)
    const int s    = v & (HW4 - 1);              // float4 offset within plane
    const int base = n_i * (CC * HW4) + s;       // channel 0 of this image

    const float4 sg = ldcs4(seg + v);
    const float4 x0 = ldcs4(x + base);
    const float4 x1 = ldcs4(x + base + HW4);
    const float4 x2 = ldcs4(x + base + 2 * HW4);
    const float4 a0 = ldcs4(ae + base);
    const float4 a1 = ldcs4(ae + base + HW4);
    const float4 a2 = ldcs4(ae + base + 2 * HW4);

    {
        float d0 = a0.x - x0.x, d1 = a1.x - x1.x, d2 = a2.x - x2.x;
        float d  = d0 * d0 + d1 * d1 + d2 * d2;
        ts += d;
        const bool p = sg.x > 0.5f;
        ps  += p ? d : 0.f;
        cnt += p ? 1u : 0u;
    }
    {
        float d0 = a0.y - x0.y, d1 = a1.y - x1.y, d2 = a2.y - x2.y;
        float d  = d0 * d0 + d1 * d1 + d2 * d2;
        ts += d;
        const bool p = sg.y > 0.5f;
        ps  += p ? d : 0.f;
        cnt += p ? 1u : 0u;
    }
    {
        float d0 = a0.z - x0.z, d1 = a1.z - x1.z, d2 = a2.z - x2.z;
        float d  = d0 * d0 + d1 * d1 + d2 * d2;
        ts += d;
        const bool p = sg.z > 0.5f;
        ps  += p ? d : 0.f;
        cnt += p ? 1u : 0u;
    }
    {
        float d0 = a0.w - x0.w, d1 = a1.w - x1.w, d2 = a2.w - x2.w;
        float d  = d0 * d0 + d1 * d1 + d2 * d2;
        ts += d;
        const bool p = sg.w > 0.5f;
        ps  += p ? d : 0.f;
        cnt += p ? 1u : 0u;
    }
}

__global__ void __launch_bounds__(NTHREADS, 6)
wmse_reduce_kernel(const float4* __restrict__ x,
                   const float4* __restrict__ ae,
                   const float4* __restrict__ seg,
                   float* __restrict__ out)
{
    float ts = 0.f;        // total sum of diff^2
    float ps = 0.f;        // sum of diff^2 where seg > 0.5
    unsigned int cnt = 0;  // positive spatial positions

    const int gtid = blockIdx.x * NTHREADS + threadIdx.x;

    // 4 full grid-stride iterations (no bounds checks), then one guarded
    // remainder iteration handled by the first REM threads (coalesced).
    #pragma unroll
    for (int it = 0; it < FULL_ITERS; ++it) {
        do_group(x, ae, seg, gtid + it * TOTTHREADS, ts, ps, cnt);
    }
    if (gtid < REM) {
        do_group(x, ae, seg, gtid + FULL_ITERS * TOTTHREADS, ts, ps, cnt);
    }

    // ---- warp reduction (fixed tree order) ----
    #pragma unroll
    for (int off = 16; off > 0; off >>= 1) {
        ts  += __shfl_down_sync(0xffffffffu, ts,  off);
        ps  += __shfl_down_sync(0xffffffffu, ps,  off);
        cnt += __shfl_down_sync(0xffffffffu, cnt, off);
    }

    // ---- block reduction via shared memory (fixed order) ----
    __shared__ float        s_ts[NTHREADS / 32];
    __shared__ float        s_ps[NTHREADS / 32];
    __shared__ unsigned int s_ct[NTHREADS / 32];
    __shared__ bool         s_is_last;

    const int tid  = threadIdx.x;
    const int lane = tid & 31;
    const int wid  = tid >> 5;
    if (lane == 0) { s_ts[wid] = ts; s_ps[wid] = ps; s_ct[wid] = cnt; }
    __syncthreads();

    if (tid == 0) {
        float tsum = 0.f, psum = 0.f;
        unsigned int c = 0;
        #pragma unroll
        for (int i = 0; i < NTHREADS / 32; ++i) {
            tsum += s_ts[i]; psum += s_ps[i]; c += s_ct[i];
        }
        g_part_ts[blockIdx.x] = tsum;
        g_part_ps[blockIdx.x] = psum;
        g_part_ct[blockIdx.x] = c;

        __threadfence();                         // publish partials
        const unsigned int prev = atomicAdd(&g_done, 1u);
        s_is_last = (prev == NBLOCKS - 1u);
    }
    __syncthreads();

    if (!s_is_last) return;

    // ================= last CTA: fused deterministic epilogue =================
    __threadfence();  // order partial reads after counter observation

    // Each thread sums up to 4 slots (idx, idx+256, idx+512, idx+768<888)
    // in fixed sequential order; reads hit L2 (just written by peer SMs).
    double fts = 0.0, fps = 0.0;
    unsigned long long fct = 0;
    #pragma unroll
    for (int i = 0; i < 4; ++i) {
        const int idx = tid + i * NTHREADS;
        if (idx < NBLOCKS) {
            fts += (double)__ldcg(&g_part_ts[idx]);
            fps += (double)__ldcg(&g_part_ps[idx]);
            fct += (unsigned long long)__ldcg(&g_part_ct[idx]);
        }
    }

    // Fixed-topology shared-memory tree reduction (deterministic).
    __shared__ double d_ts[NTHREADS];
    __shared__ double d_ps[NTHREADS];
    __shared__ unsigned long long d_ct[NTHREADS];
    d_ts[tid] = fts; d_ps[tid] = fps; d_ct[tid] = fct;
    __syncthreads();

    #pragma unroll
    for (int off = NTHREADS / 2; off > 0; off >>= 1) {
        if (tid < off) {
            d_ts[tid] += d_ts[tid + off];
            d_ps[tid] += d_ps[tid + off];
            d_ct[tid] += d_ct[tid + off];
        }
        __syncthreads();
    }

    if (tid == 0) {
        const double pos_num   = (double)d_ct[0];
        const double total     = (double)NHW;
        const double neg_num   = total - pos_num;
        const double pos_ratio = pos_num / total;
        const double neg_ratio = 1.0 - pos_ratio;
        const double cf        = (double)CC;
        const double pos_sum   = d_ps[0];
        const double neg_sum   = d_ts[0] - d_ps[0];
        const double mse_pos   = pos_sum / (pos_num * cf);
        const double mse_neg   = neg_sum / (neg_num * cf);
        out[0] = (float)(pos_ratio * mse_neg + neg_ratio * mse_pos);

        g_done = 0;   // reset for the next call / graph replay
    }
}

extern "C" void kernel_launch(void* const* d_in, const int* in_sizes, int n_in,
                              void* d_out, int out_size)
{
    const float4* x   = (const float4*)d_in[0];   // x       (16,3,512,512) f32
    const float4* ae  = (const float4*)d_in[1];   // out_ae  (16,3,512,512) f32
    const float4* seg = (const float4*)d_in[2];   // out_seg (16,1,512,512) f32
    float* out = (float*)d_out;

    wmse_reduce_kernel<<<NBLOCKS, NTHREADS>>>(x, ae, seg, out);
}

// round 17
// speedup vs baseline: 1.2399x; 1.1872x over previous
#include <cuda_runtime.h>

// Shapes fixed by the reference: n=16, c=3, h=w=512
#define HW      262144          // 512*512
#define NB      16
#define CC      3
#define NHW     (NB * HW)       // 4194304 spatial positions (n,1,h,w)
#define HW4     (HW / 4)        // float4 elements per channel plane = 65536 = 2^16
#define NVEC    (NHW / 4)       // float4 elements in seg = 1048576

// Single-wave persistent grid: 8 CTAs/SM x 148 SMs = 1184 CTAs, all co-resident.
#define NBLOCKS   1184
#define NTHREADS  256
#define TOTTHREADS (NBLOCKS * NTHREADS)              // 303104
#define FULL_ITERS 3                                 // 3 * 303104 = 909312
#define REM        (NVEC - FULL_ITERS * TOTTHREADS)  // 139264 remainder float4s

// Per-block partials (device globals; no allocation allowed).
__device__ float        g_part_ts[NBLOCKS];
__device__ float        g_part_ps[NBLOCKS];
__device__ unsigned int g_part_ct[NBLOCKS];
// Completion counter: zero-init at load; last block resets it each call.
__device__ unsigned int g_done;

// Streaming (evict-first) float4 load: data is single-use per launch.
static __device__ __forceinline__ float4 ldcs4(const float4* p) {
    return __ldcs(p);
}

// One float4-group of work, channel-interleaved to keep live ranges small:
// seg lane -> 4 predicates, then (x_c, ae_c) pairs consumed immediately.
static __device__ __forceinline__ void do_group(
    const float4* __restrict__ x, const float4* __restrict__ ae,
    const float4* __restrict__ seg, int v,
    float& ts, float& ps, unsigned int& cnt)
{
    const int n_i  = v >> 16;                    // image index  (v / HW4)
    const int s    = v & (HW4 - 1);              // float4 offset within plane
    const int base = n_i * (CC * HW4) + s;       // channel 0 of this image

    const float4 sg = ldcs4(seg + v);
    const bool p0 = sg.x > 0.5f;
    const bool p1 = sg.y > 0.5f;
    const bool p2 = sg.z > 0.5f;
    const bool p3 = sg.w > 0.5f;
    cnt += (p0 ? 1u : 0u) + (p1 ? 1u : 0u) + (p2 ? 1u : 0u) + (p3 ? 1u : 0u);

    #pragma unroll
    for (int c = 0; c < CC; ++c) {
        const float4 xc = ldcs4(x  + base + c * HW4);
        const float4 ac = ldcs4(ae + base + c * HW4);
        {
            const float d = ac.x - xc.x, d2 = d * d;
            ts += d2; ps += p0 ? d2 : 0.f;
        }
        {
            const float d = ac.y - xc.y, d2 = d * d;
            ts += d2; ps += p1 ? d2 : 0.f;
        }
        {
            const float d = ac.z - xc.z, d2 = d * d;
            ts += d2; ps += p2 ? d2 : 0.f;
        }
        {
            const float d = ac.w - xc.w, d2 = d * d;
            ts += d2; ps += p3 ? d2 : 0.f;
        }
    }
}

__global__ void __launch_bounds__(NTHREADS, 8)
wmse_reduce_kernel(const float4* __restrict__ x,
                   const float4* __restrict__ ae,
                   const float4* __restrict__ seg,
                   float* __restrict__ out)
{
    float ts = 0.f;        // total sum of diff^2
    float ps = 0.f;        // sum of diff^2 where seg > 0.5
    unsigned int cnt = 0;  // positive spatial positions

    const int gtid = blockIdx.x * NTHREADS + threadIdx.x;

    // 3 full grid-stride iterations (no bounds checks), then one guarded
    // remainder iteration handled by the first REM threads (coalesced).
    #pragma unroll
    for (int it = 0; it < FULL_ITERS; ++it) {
        do_group(x, ae, seg, gtid + it * TOTTHREADS, ts, ps, cnt);
    }
    if (gtid < REM) {
        do_group(x, ae, seg, gtid + FULL_ITERS * TOTTHREADS, ts, ps, cnt);
    }

    // ---- warp reduction (fixed tree order) ----
    #pragma unroll
    for (int off = 16; off > 0; off >>= 1) {
        ts  += __shfl_down_sync(0xffffffffu, ts,  off);
        ps  += __shfl_down_sync(0xffffffffu, ps,  off);
        cnt += __shfl_down_sync(0xffffffffu, cnt, off);
    }

    // ---- block reduction via shared memory (fixed order) ----
    __shared__ float        s_ts[NTHREADS / 32];
    __shared__ float        s_ps[NTHREADS / 32];
    __shared__ unsigned int s_ct[NTHREADS / 32];
    __shared__ bool         s_is_last;

    const int tid  = threadIdx.x;
    const int lane = tid & 31;
    const int wid  = tid >> 5;
    if (lane == 0) { s_ts[wid] = ts; s_ps[wid] = ps; s_ct[wid] = cnt; }
    __syncthreads();

    if (tid == 0) {
        float tsum = 0.f, psum = 0.f;
        unsigned int c = 0;
        #pragma unroll
        for (int i = 0; i < NTHREADS / 32; ++i) {
            tsum += s_ts[i]; psum += s_ps[i]; c += s_ct[i];
        }
        g_part_ts[blockIdx.x] = tsum;
        g_part_ps[blockIdx.x] = psum;
        g_part_ct[blockIdx.x] = c;

        __threadfence();                         // publish partials
        const unsigned int prev = atomicAdd(&g_done, 1u);
        s_is_last = (prev == NBLOCKS - 1u);
    }
    __syncthreads();

    if (!s_is_last) return;

    // ================= last CTA: fused deterministic epilogue =================
    // All-float (keeps the whole kernel's register allocation at the 32-reg cap);
    // fixed summation order -> bitwise deterministic. 1184 float partials summed
    // in a fixed tree: ~1e-7 relative error, far under the 1e-3 gate.
    __threadfence();  // order partial reads after counter observation

    float fts = 0.f, fps = 0.f;
    unsigned int fct = 0;
    #pragma unroll
    for (int i = 0; i < 5; ++i) {                // ceil(1184/256) = 5
        const int idx = tid + i * NTHREADS;
        if (idx < NBLOCKS) {
            fts += __ldcg(&g_part_ts[idx]);
            fps += __ldcg(&g_part_ps[idx]);
            fct += __ldcg(&g_part_ct[idx]);
        }
    }

    __shared__ float        d_ts[NTHREADS];
    __shared__ float        d_ps[NTHREADS];
    __shared__ unsigned int d_ct[NTHREADS];
    d_ts[tid] = fts; d_ps[tid] = fps; d_ct[tid] = fct;
    __syncthreads();

    #pragma unroll
    for (int off = NTHREADS / 2; off > 0; off >>= 1) {
        if (tid < off) {
            d_ts[tid] += d_ts[tid + off];
            d_ps[tid] += d_ps[tid + off];
            d_ct[tid] += d_ct[tid + off];
        }
        __syncthreads();
    }

    if (tid == 0) {
        const float pos_num   = (float)d_ct[0];
        const float total     = (float)NHW;
        const float neg_num   = total - pos_num;
        const float pos_ratio = pos_num / total;
        const float neg_ratio = 1.0f - pos_ratio;
        const float cf        = (float)CC;
        const float pos_sum   = d_ps[0];
        const float neg_sum   = d_ts[0] - d_ps[0];
        const float mse_pos   = pos_sum / (pos_num * cf);
        const float mse_neg   = neg_sum / (neg_num * cf);
        out[0] = pos_ratio * mse_neg + neg_ratio * mse_pos;

        g_done = 0;   // reset for the next call / graph replay
    }
}

extern "C" void kernel_launch(void* const* d_in, const int* in_sizes, int n_in,
                              void* d_out, int out_size)
{
    const float4* x   = (const float4*)d_in[0];   // x       (16,3,512,512) f32
    const float4* ae  = (const float4*)d_in[1];   // out_ae  (16,3,512,512) f32
    const float4* seg = (const float4*)d_in[2];   // out_seg (16,1,512,512) f32
    float* out = (float*)d_out;

    wmse_reduce_kernel<<<NBLOCKS, NTHREADS>>>(x, ae, seg, out);
}